// round 13
// baseline (speedup 1.0000x reference)
#include <cuda_runtime.h>
#include <cstdint>

// ---------- hardware tanh (1 MUFU op) ----------
__device__ __forceinline__ float tanh_(float x) {
    float r;
    asm("tanh.approx.f32 %0, %1;" : "=f"(r) : "f"(x));
    return r;
}

// volatile LDS.128: uncacheable, unhoistable -> kills ptxas weight-caching
__device__ __forceinline__ float4 lds128v(const float* p) {
    float4 v;
    unsigned saddr = (unsigned)__cvta_generic_to_shared(p);
    asm volatile("ld.volatile.shared.v4.f32 {%0,%1,%2,%3}, [%4];"
                 : "=f"(v.x), "=f"(v.y), "=f"(v.z), "=f"(v.w)
                 : "r"(saddr));
    return v;
}

#define TT 14
#define HH 7
#define FF 12
#define NTHR 128
#define BLKS_PER_SM 5

// Gate-folded LSTM cell update. Weights pre-scaled so that:
//  - i,f,o rows produce z' = 0.5*z_true  (sigmoid = 0.5*tanh(z')+0.5)
//  - hidden state is carried as h' = 2*h_true (consumers pre-scaled by 0.5)
__device__ __forceinline__ float cell_update(const float z[4], float& c) {
    float ti = tanh_(z[0]);
    float tf = tanh_(z[1]);
    float tg = tanh_(z[2]);
    float to = tanh_(z[3]);
    float iv = fmaf(0.5f, ti, 0.5f);
    float fv = fmaf(0.5f, tf, 0.5f);
    float cv = fmaf(fv, c, iv * tg);
    c = cv;
    return (to + 1.0f) * tanh_(cv);   // = 2*h_true
}

// EB-templated block body: EB=1 compiles with NO second chain.
template <int EB>
__device__ __forceinline__ void run_block(
    const float* __restrict__ x, float* __restrict__ out, int B, int base,
    const float* s_l0, const float* s_l1, const float* s_w1,
    const float* s_w2, float blin, float b2v, float* s_u, int tid)
{
    const int cap = EB * NTHR;
    const int nb = min(cap, B - base);   // block-uniform
    if (nb <= 0) return;
    const int cnt = nb * TT;

    // ---- phase 1: coalesced linear1 + tanh ----
    {
        float4 wA = *(const float4*)&s_w1[0];
        float4 wB = *(const float4*)&s_w1[4];
        float4 wC = *(const float4*)&s_w1[8];
        const float* xb = x + (long)base * TT * FF;
        const int iters = (cnt + NTHR - 1) / NTHR;
#pragma unroll 1
        for (int it = 0; it < iters; it++) {
            int idx = it * NTHR + tid;
            if (idx < cnt) {
                int bl = idx / TT;
                int t  = idx - bl * TT;
                const float4* px = (const float4*)(xb + (long)idx * FF);
                float4 a0 = px[0], a1 = px[1], a2 = px[2];
                float s = blin;
                s = fmaf(a0.x, wA.x, s); s = fmaf(a0.y, wA.y, s);
                s = fmaf(a0.z, wA.z, s); s = fmaf(a0.w, wA.w, s);
                s = fmaf(a1.x, wB.x, s); s = fmaf(a1.y, wB.y, s);
                s = fmaf(a1.z, wB.z, s); s = fmaf(a1.w, wB.w, s);
                s = fmaf(a2.x, wC.x, s); s = fmaf(a2.y, wC.y, s);
                s = fmaf(a2.z, wC.z, s); s = fmaf(a2.w, wC.w, s);
                s_u[bl * 15 + t] = tanh_(s);
            }
        }
    }
    __syncthreads();

    if (tid >= nb) return;

    int ur[EB];
#pragma unroll
    for (int e = 0; e < EB; e++) ur[e] = min(e * NTHR + tid, nb - 1);

    float h0[EB][HH], c0[EB][HH], h1[EB][HH], c1[EB][HH];
#pragma unroll
    for (int e = 0; e < EB; e++)
#pragma unroll
        for (int j = 0; j < HH; j++) {
            h0[e][j] = 0.f; c0[e][j] = 0.f; h1[e][j] = 0.f; c1[e][j] = 0.f;
        }

#pragma unroll 1
    for (int t = 0; t < TT; t++) {
        float xin[EB];
#pragma unroll
        for (int e = 0; e < EB; e++) xin[e] = s_u[ur[e] * 15 + t];

        // ---- layer 0: per j, merged record [b_i,b_f,b_g,b_o | 4 x (wih, whh0..6)]
        float hn[EB][HH];
#pragma unroll
        for (int j = 0; j < HH; j++) {
            const float* rec = &s_l0[j * 36];
            float4 bz = lds128v(rec);
            const float bsel[4] = {bz.x, bz.y, bz.z, bz.w};
            float z[EB][4];
#pragma unroll
            for (int g = 0; g < 4; g++) {
                float4 r0 = lds128v(rec + 4 + g * 8);
                float4 r1 = lds128v(rec + 8 + g * 8);
#pragma unroll
                for (int e = 0; e < EB; e++) {
                    float zz = fmaf(xin[e], r0.x, bsel[g]);
                    zz = fmaf(h0[e][0], r0.y, zz);
                    zz = fmaf(h0[e][1], r0.z, zz);
                    zz = fmaf(h0[e][2], r0.w, zz);
                    zz = fmaf(h0[e][3], r1.x, zz);
                    zz = fmaf(h0[e][4], r1.y, zz);
                    zz = fmaf(h0[e][5], r1.z, zz);
                    zz = fmaf(h0[e][6], r1.w, zz);
                    z[e][g] = zz;
                }
            }
#pragma unroll
            for (int e = 0; e < EB; e++)
                hn[e][j] = cell_update(z[e], c0[e][j]);
        }

        // ---- layer 1: row r = g*7+j, 16 floats [b, wih0..6, whh0..6, pad]
        float hn1[EB][HH];
#pragma unroll
        for (int j = 0; j < HH; j++) {
            float z[EB][4];
#pragma unroll
            for (int g = 0; g < 4; g++) {
                const float* rp = &s_l1[(g * HH + j) * 16];
                float4 r0 = lds128v(rp);
                float4 r1 = lds128v(rp + 4);
                float4 r2 = lds128v(rp + 8);
                float4 r3 = lds128v(rp + 12);
#pragma unroll
                for (int e = 0; e < EB; e++) {
                    float zz = r0.x;
                    zz = fmaf(hn[e][0], r0.y, zz);
                    zz = fmaf(hn[e][1], r0.z, zz);
                    zz = fmaf(hn[e][2], r0.w, zz);
                    zz = fmaf(hn[e][3], r1.x, zz);
                    zz = fmaf(hn[e][4], r1.y, zz);
                    zz = fmaf(hn[e][5], r1.z, zz);
                    zz = fmaf(hn[e][6], r1.w, zz);
                    zz = fmaf(h1[e][0], r2.x, zz);
                    zz = fmaf(h1[e][1], r2.y, zz);
                    zz = fmaf(h1[e][2], r2.z, zz);
                    zz = fmaf(h1[e][3], r2.w, zz);
                    zz = fmaf(h1[e][4], r3.x, zz);
                    zz = fmaf(h1[e][5], r3.y, zz);
                    zz = fmaf(h1[e][6], r3.z, zz);
                    z[e][g] = zz;
                }
            }
#pragma unroll
            for (int e = 0; e < EB; e++)
                hn1[e][j] = cell_update(z[e], c1[e][j]);
        }

#pragma unroll
        for (int e = 0; e < EB; e++)
#pragma unroll
            for (int j = 0; j < HH; j++) {
                h0[e][j] = hn[e][j]; h1[e][j] = hn1[e][j];
            }
    }

    // ---- phase 3 (s_w2 pre-scaled by 0.5 to undo h' = 2h) ----
#pragma unroll
    for (int e = 0; e < EB; e++) {
        float acc = b2v;
#pragma unroll
        for (int j = 0; j < HH; j++) {
            acc = fmaf(h0[e][j], s_w2[j], acc);
            acc = fmaf(h1[e][j], s_w2[HH + j], acc);
        }
        int gb = base + e * NTHR + tid;
        if (gb < B) out[gb] = acc;
    }
}

__global__ __launch_bounds__(NTHR, BLKS_PER_SM)
void lstm_fused_kernel(
    const float* __restrict__ x,
    const float* __restrict__ w1,  const float* __restrict__ b1,
    const float* __restrict__ wih0, const float* __restrict__ whh0,
    const float* __restrict__ bih0, const float* __restrict__ bhh0,
    const float* __restrict__ wih1, const float* __restrict__ whh1,
    const float* __restrict__ bih1, const float* __restrict__ bhh1,
    const float* __restrict__ w2,  const float* __restrict__ b2,
    float* __restrict__ out, int B, int nfull)
{
    __shared__ __align__(16) float s_l0[HH * 36];
    __shared__ __align__(16) float s_l1[28 * 16];
    __shared__ __align__(16) float s_w1[12];
    __shared__ float s_w2[2 * HH];
    __shared__ float s_b1lin, s_b2;
    __shared__ float s_u[2 * NTHR * 15];

    const int tid = threadIdx.x;

    for (int r = tid; r < 28; r += NTHR) {
        int g = r / 7, j = r % 7;
        const bool ifo = (g != 2);
        const float sb = ifo ? 0.5f : 1.0f;     // bias scale
        const float sx = ifo ? 0.5f : 1.0f;     // non-hidden-input weight scale
        const float sh = ifo ? 0.25f : 0.5f;    // hidden-input weight scale

        s_l0[j * 36 + g] = (bih0[r] + bhh0[r]) * sb;
        s_l0[j * 36 + 4 + g * 8 + 0] = wih0[r] * sx;
#pragma unroll
        for (int k = 0; k < 7; k++)
            s_l0[j * 36 + 4 + g * 8 + 1 + k] = whh0[r * 7 + k] * sh;

        s_l1[r * 16 + 0] = (bih1[r] + bhh1[r]) * sb;
#pragma unroll
        for (int k = 0; k < 7; k++) s_l1[r * 16 + 1 + k] = wih1[r * 7 + k] * sh;
#pragma unroll
        for (int k = 0; k < 7; k++) s_l1[r * 16 + 8 + k] = whh1[r * 7 + k] * sh;
        s_l1[r * 16 + 15] = 0.f;
    }
    if (tid < 2 * HH) s_w2[tid] = w2[tid] * 0.5f;   // undo h' = 2h
    if (tid < FF)     s_w1[tid] = w1[tid];
    if (tid == 0) { s_b1lin = b1[0]; s_b2 = b2[0]; }
    __syncthreads();

    const int bid = blockIdx.x;
    if (bid < nfull) {
        run_block<2>(x, out, B, bid * (2 * NTHR),
                     s_l0, s_l1, s_w1, s_w2, s_b1lin, s_b2, s_u, tid);
    } else {
        run_block<1>(x, out, B, nfull * (2 * NTHR) + (bid - nfull) * NTHR,
                     s_l0, s_l1, s_w1, s_w2, s_b1lin, s_b2, s_u, tid);
    }
}

extern "C" void kernel_launch(void* const* d_in, const int* in_sizes, int n_in,
                              void* d_out, int out_size) {
    const float* x    = (const float*)d_in[0];
    const float* w1   = (const float*)d_in[1];
    const float* b1   = (const float*)d_in[2];
    const float* wih0 = (const float*)d_in[3];
    const float* whh0 = (const float*)d_in[4];
    const float* bih0 = (const float*)d_in[5];
    const float* bhh0 = (const float*)d_in[6];
    const float* wih1 = (const float*)d_in[7];
    const float* whh1 = (const float*)d_in[8];
    const float* bih1 = (const float*)d_in[9];
    const float* bhh1 = (const float*)d_in[10];
    const float* w2   = (const float*)d_in[11];
    const float* b2   = (const float*)d_in[12];
    float* out = (float*)d_out;

    const int B = out_size;                 // 262144

    int sms = 148;
    cudaDeviceGetAttribute(&sms, cudaDevAttrMultiProcessorCount, 0);

    int grid   = 2 * BLKS_PER_SM * sms;              // exact 2 waves @ 5/SM
    int chunks = (B + NTHR - 1) / NTHR;              // 2048 chunks of 128
    if (chunks > 2 * grid) grid = (chunks + 1) / 2;  // safety for huge B
    int nfull = chunks - grid;                       // EB=2 blocks
    if (nfull < 0) nfull = 0;
    if (nfull > grid) nfull = grid;

    lstm_fused_kernel<<<grid, NTHR>>>(x, w1, b1, wih0, whh0, bih0, bhh0,
                                      wih1, whh1, bih1, bhh1, w2, b2,
                                      out, B, nfull);
}

// round 14
// speedup vs baseline: 1.1522x; 1.1522x over previous
#include <cuda_runtime.h>
#include <cstdint>

#define TT 14
#define HH 7
#define FF 12
#define NTHR 128

// constant-bank weight image: [l0 252][l1 448][w1 12][w2 14][blin,b2]
#define L0OFF 0
#define L1OFF 252
#define W1OFF 700
#define W2OFF 712
#define BOFF  726
#define WTOTAL 728

__device__    float g_prep[WTOTAL];
__constant__  float c_all[WTOTAL];

// ---------- hardware tanh (1 MUFU op) ----------
__device__ __forceinline__ float tanh_(float x) {
    float r;
    asm("tanh.approx.f32 %0, %1;" : "=f"(r) : "f"(x));
    return r;
}

// Gate-folded LSTM cell update (weights pre-scaled; h carried as h'=2h).
__device__ __forceinline__ float cell_update(const float z[4], float& c) {
    float ti = tanh_(z[0]);
    float tf = tanh_(z[1]);
    float tg = tanh_(z[2]);
    float to = tanh_(z[3]);
    float iv = fmaf(0.5f, ti, 0.5f);
    float fv = fmaf(0.5f, tf, 0.5f);
    float cv = fmaf(fv, c, iv * tg);
    c = cv;
    return (to + 1.0f) * tanh_(cv);   // = 2*h_true
}

// ---------- prep kernel: scale + layout weights into g_prep ----------
__global__ void prep_weights(
    const float* __restrict__ w1,  const float* __restrict__ b1,
    const float* __restrict__ wih0, const float* __restrict__ whh0,
    const float* __restrict__ bih0, const float* __restrict__ bhh0,
    const float* __restrict__ wih1, const float* __restrict__ whh1,
    const float* __restrict__ bih1, const float* __restrict__ bhh1,
    const float* __restrict__ w2,  const float* __restrict__ b2)
{
    int r = threadIdx.x;
    if (r < 28) {
        int g = r / 7, j = r % 7;
        const bool ifo = (g != 2);
        const float sb = ifo ? 0.5f : 1.0f;     // bias scale
        const float sx = ifo ? 0.5f : 1.0f;     // non-hidden-input weight scale
        const float sh = ifo ? 0.25f : 0.5f;    // hidden-input weight scale

        g_prep[L0OFF + j * 36 + g] = (bih0[r] + bhh0[r]) * sb;
        g_prep[L0OFF + j * 36 + 4 + g * 8 + 0] = wih0[r] * sx;
#pragma unroll
        for (int k = 0; k < 7; k++)
            g_prep[L0OFF + j * 36 + 4 + g * 8 + 1 + k] = whh0[r * 7 + k] * sh;

        g_prep[L1OFF + r * 16 + 0] = (bih1[r] + bhh1[r]) * sb;
#pragma unroll
        for (int k = 0; k < 7; k++)
            g_prep[L1OFF + r * 16 + 1 + k] = wih1[r * 7 + k] * sh;
#pragma unroll
        for (int k = 0; k < 7; k++)
            g_prep[L1OFF + r * 16 + 8 + k] = whh1[r * 7 + k] * sh;
        g_prep[L1OFF + r * 16 + 15] = 0.f;
    }
    if (r < FF)     g_prep[W1OFF + r] = w1[r];
    if (r < 2 * HH) g_prep[W2OFF + r] = w2[r] * 0.5f;   // undo h' = 2h
    if (r == 0) { g_prep[BOFF + 0] = b1[0]; g_prep[BOFF + 1] = b2[0]; }
}

// EB-templated block body: EB=1 compiles with NO second chain.
template <int EB>
__device__ __forceinline__ void run_block(
    const float* __restrict__ x, float* __restrict__ out, int B, int base,
    float* s_u, int tid)
{
    const int cap = EB * NTHR;
    const int nb = min(cap, B - base);   // block-uniform
    if (nb <= 0) return;
    const int cnt = nb * TT;

    // ---- phase 1: coalesced linear1 + tanh (weights from constant bank) ----
    {
        const float blin = c_all[BOFF + 0];
        const int iters = (cnt + NTHR - 1) / NTHR;
        const float* xb = x + (long)base * TT * FF;
#pragma unroll 1
        for (int it = 0; it < iters; it++) {
            int idx = it * NTHR + tid;
            if (idx < cnt) {
                int bl = idx / TT;
                int t  = idx - bl * TT;
                const float4* px = (const float4*)(xb + (long)idx * FF);
                float4 a0 = px[0], a1 = px[1], a2 = px[2];
                float s = blin;
                s = fmaf(a0.x, c_all[W1OFF + 0], s);
                s = fmaf(a0.y, c_all[W1OFF + 1], s);
                s = fmaf(a0.z, c_all[W1OFF + 2], s);
                s = fmaf(a0.w, c_all[W1OFF + 3], s);
                s = fmaf(a1.x, c_all[W1OFF + 4], s);
                s = fmaf(a1.y, c_all[W1OFF + 5], s);
                s = fmaf(a1.z, c_all[W1OFF + 6], s);
                s = fmaf(a1.w, c_all[W1OFF + 7], s);
                s = fmaf(a2.x, c_all[W1OFF + 8], s);
                s = fmaf(a2.y, c_all[W1OFF + 9], s);
                s = fmaf(a2.z, c_all[W1OFF + 10], s);
                s = fmaf(a2.w, c_all[W1OFF + 11], s);
                s_u[bl * 15 + t] = tanh_(s);
            }
        }
    }
    __syncthreads();

    if (tid >= nb) return;

    int ur[EB];
#pragma unroll
    for (int e = 0; e < EB; e++) ur[e] = min(e * NTHR + tid, nb - 1);

    float h0[EB][HH], c0[EB][HH], h1[EB][HH], c1[EB][HH];
#pragma unroll
    for (int e = 0; e < EB; e++)
#pragma unroll
        for (int j = 0; j < HH; j++) {
            h0[e][j] = 0.f; c0[e][j] = 0.f; h1[e][j] = 0.f; c1[e][j] = 0.f;
        }

#pragma unroll 1
    for (int t = 0; t < TT; t++) {
        float xin[EB];
#pragma unroll
        for (int e = 0; e < EB; e++) xin[e] = s_u[ur[e] * 15 + t];

        // ---- layer 0 ----
        float hn[EB][HH];
#pragma unroll
        for (int j = 0; j < HH; j++) {
            float z[EB][4];
#pragma unroll
            for (int g = 0; g < 4; g++) {
                const int rb = L0OFF + j * 36;
                const int wb = rb + 4 + g * 8;
#pragma unroll
                for (int e = 0; e < EB; e++) {
                    float zz = fmaf(xin[e], c_all[wb + 0], c_all[rb + g]);
                    zz = fmaf(h0[e][0], c_all[wb + 1], zz);
                    zz = fmaf(h0[e][1], c_all[wb + 2], zz);
                    zz = fmaf(h0[e][2], c_all[wb + 3], zz);
                    zz = fmaf(h0[e][3], c_all[wb + 4], zz);
                    zz = fmaf(h0[e][4], c_all[wb + 5], zz);
                    zz = fmaf(h0[e][5], c_all[wb + 6], zz);
                    zz = fmaf(h0[e][6], c_all[wb + 7], zz);
                    z[e][g] = zz;
                }
            }
#pragma unroll
            for (int e = 0; e < EB; e++)
                hn[e][j] = cell_update(z[e], c0[e][j]);
        }

        // ---- layer 1 ----
        float hn1[EB][HH];
#pragma unroll
        for (int j = 0; j < HH; j++) {
            float z[EB][4];
#pragma unroll
            for (int g = 0; g < 4; g++) {
                const int rp = L1OFF + (g * HH + j) * 16;
#pragma unroll
                for (int e = 0; e < EB; e++) {
                    float zz = c_all[rp + 0];
                    zz = fmaf(hn[e][0], c_all[rp + 1], zz);
                    zz = fmaf(hn[e][1], c_all[rp + 2], zz);
                    zz = fmaf(hn[e][2], c_all[rp + 3], zz);
                    zz = fmaf(hn[e][3], c_all[rp + 4], zz);
                    zz = fmaf(hn[e][4], c_all[rp + 5], zz);
                    zz = fmaf(hn[e][5], c_all[rp + 6], zz);
                    zz = fmaf(hn[e][6], c_all[rp + 7], zz);
                    zz = fmaf(h1[e][0], c_all[rp + 8], zz);
                    zz = fmaf(h1[e][1], c_all[rp + 9], zz);
                    zz = fmaf(h1[e][2], c_all[rp + 10], zz);
                    zz = fmaf(h1[e][3], c_all[rp + 11], zz);
                    zz = fmaf(h1[e][4], c_all[rp + 12], zz);
                    zz = fmaf(h1[e][5], c_all[rp + 13], zz);
                    zz = fmaf(h1[e][6], c_all[rp + 14], zz);
                    z[e][g] = zz;
                }
            }
#pragma unroll
            for (int e = 0; e < EB; e++)
                hn1[e][j] = cell_update(z[e], c1[e][j]);
        }

#pragma unroll
        for (int e = 0; e < EB; e++)
#pragma unroll
            for (int j = 0; j < HH; j++) {
                h0[e][j] = hn[e][j]; h1[e][j] = hn1[e][j];
            }
    }

    // ---- phase 3 ----
#pragma unroll
    for (int e = 0; e < EB; e++) {
        float acc = c_all[BOFF + 1];
#pragma unroll
        for (int j = 0; j < HH; j++) {
            acc = fmaf(h0[e][j], c_all[W2OFF + j], acc);
            acc = fmaf(h1[e][j], c_all[W2OFF + HH + j], acc);
        }
        int gb = base + e * NTHR + tid;
        if (gb < B) out[gb] = acc;
    }
}

__global__ __launch_bounds__(NTHR, 4)
void lstm_fused_kernel(const float* __restrict__ x,
                       float* __restrict__ out, int B, int nfull)
{
    __shared__ float s_u[2 * NTHR * 15];
    const int tid = threadIdx.x;
    const int bid = blockIdx.x;
    if (bid < nfull) {
        run_block<2>(x, out, B, bid * (2 * NTHR), s_u, tid);
    } else {
        run_block<1>(x, out, B, nfull * (2 * NTHR) + (bid - nfull) * NTHR,
                     s_u, tid);
    }
}

extern "C" void kernel_launch(void* const* d_in, const int* in_sizes, int n_in,
                              void* d_out, int out_size) {
    const float* x    = (const float*)d_in[0];
    const float* w1   = (const float*)d_in[1];
    const float* b1   = (const float*)d_in[2];
    const float* wih0 = (const float*)d_in[3];
    const float* whh0 = (const float*)d_in[4];
    const float* bih0 = (const float*)d_in[5];
    const float* bhh0 = (const float*)d_in[6];
    const float* wih1 = (const float*)d_in[7];
    const float* whh1 = (const float*)d_in[8];
    const float* bih1 = (const float*)d_in[9];
    const float* bhh1 = (const float*)d_in[10];
    const float* w2   = (const float*)d_in[11];
    const float* b2   = (const float*)d_in[12];
    float* out = (float*)d_out;

    const int B = out_size;                 // 262144

    // 1) scale + layout weights into a __device__ buffer
    prep_weights<<<1, 32>>>(w1, b1, wih0, whh0, bih0, bhh0,
                            wih1, whh1, bih1, bhh1, w2, b2);

    // 2) copy into the constant bank (D2D memcpy node; graph-capturable)
    void* gp = nullptr;
    cudaGetSymbolAddress(&gp, g_prep);
    cudaMemcpyToSymbolAsync(c_all, gp, WTOTAL * sizeof(float), 0,
                            cudaMemcpyDeviceToDevice, 0);

    // 3) main kernel: exact 2 waves @ 4/SM, heterogeneous EB2/EB1 fill
    int sms = 148;
    cudaDeviceGetAttribute(&sms, cudaDevAttrMultiProcessorCount, 0);
    int grid   = 2 * 4 * sms;
    int chunks = (B + NTHR - 1) / NTHR;
    if (chunks > 2 * grid) grid = (chunks + 1) / 2;
    int nfull = chunks - grid;
    if (nfull < 0) nfull = 0;
    if (nfull > grid) nfull = grid;

    lstm_fused_kernel<<<grid, NTHR>>>(x, out, B, nfull);
}